// round 14
// baseline (speedup 1.0000x reference)
#include <cuda_runtime.h>
#include <cuda_fp16.h>
#include <cstdint>

// LIFNeuron dopri5 via mma.sync m16n8k16 fp16 (2-term split, 3 passes) — R12.
// = R10 with (1) 10-warp / 320-thread CTA (SMEM allows 10.6 warps; was 8),
//   (2) per-stage template specialization (dead k-loads/FMAs removed, bitwise
//   identical since skipped terms were fmaf(0, finite, acc)).

#define NWARP 10
#define THREADS (NWARP * 32)
#define ROWS_CTA (NWARP * 16)
#define BQS 130             // B row stride in float4
#define KSTR 72             // k-buffer row stride in floats (≡8 mod 32)

#define HC(x) (0.125f * (float)(x))

extern __shared__ float smf[];

#define OFF_BQ 0                          // 16 rows x BQS float4 = 8320 floats
#define OFF_K1 (16 * BQS * 4)
#define KBUF   (NWARP * 16 * KSTR)        // floats per buffer
#define OFF_K2 (OFF_K1 + KBUF)
#define OFF_SC (OFF_K2 + KBUF)
#define OFF_K5 (OFF_SC + KBUF)
#define OFF_BG (OFF_K5 + KBUF)
#define SMEM_FLOATS (OFF_BG + 64)         // 54464 floats = 217856 B

__device__ __forceinline__ void mma16(float* d, const uint32_t* a, uint32_t b0, uint32_t b1) {
    asm volatile("mma.sync.aligned.m16n8k16.row.col.f32.f16.f16.f32 "
        "{%0,%1,%2,%3}, {%4,%5,%6,%7}, {%8,%9}, {%0,%1,%2,%3};"
        : "+f"(d[0]), "+f"(d[1]), "+f"(d[2]), "+f"(d[3])
        : "r"(a[0]), "r"(a[1]), "r"(a[2]), "r"(a[3]), "r"(b0), "r"(b1));
}

__device__ __forceinline__ float gelu_f(float z) {
    return 0.5f * z * (1.0f + erff(z * 0.70710678118654752440f));
}
__device__ __forceinline__ float timefac_f(float g) {
    float e = __expf(-g);
    return 1.0f - __frcp_rn(2.0f + e);
}

// One dopri5 stage: xi-build -> D = Xi@[W|Wg] (3-pass fp16 split) -> k = phi(D)
// -> stage-specific register pulls / final combine.
template<int S>
__device__ __forceinline__ void stage_body(
    float xA[2][16], float k3A[2][16], float k4A[2][16],
    float* __restrict__ k1w, float* __restrict__ k2w,
    float* __restrict__ scw, float* __restrict__ k5w,
    const float4* __restrict__ BqT, const float* __restrict__ BG,
    int r0, int c0, bool last)
{
    constexpr float c1 = (S==1) ? HC(1.0/5.0) : (S==2) ? HC(3.0/40.0) : (S==3) ? HC(44.0/45.0)
                       : (S==4) ? HC(19372.0/6561.0) : (S==5) ? HC(9017.0/3168.0) : 0.f;
    constexpr float c2 = (S==2) ? HC(9.0/40.0) : (S==3) ? HC(-56.0/15.0)
                       : (S==4) ? HC(-25360.0/2187.0) : (S==5) ? HC(-355.0/33.0) : 0.f;
    constexpr float c3 = (S==3) ? HC(32.0/9.0) : (S==4) ? HC(64448.0/6561.0)
                       : (S==5) ? HC(46732.0/5247.0) : 0.f;
    constexpr float c4 = (S==4) ? HC(-212.0/729.0) : (S==5) ? HC(49.0/176.0) : 0.f;
    constexpr float c5 = (S==5) ? HC(-5103.0/18656.0) : 0.f;

    // ---- build xi, fp16 hi/lo split, packed A fragments ----
    uint32_t A1[4][4], A2[4][4];
    #pragma unroll
    for (int kc = 0; kc < 4; kc++)
        #pragma unroll
        for (int e = 0; e < 2; e++)
            #pragma unroll
            for (int h = 0; h < 2; h++) {
                const int m = kc * 4 + e * 2;
                const int off = (r0 + 8 * h) * KSTR + 16 * kc + 8 * e + 2 * c0;
                float a0 = xA[h][m], a1 = xA[h][m + 1];
                if constexpr (S >= 1) {
                    float2 v1 = *(const float2*)(k1w + off);
                    a0 = fmaf(c1, v1.x, a0); a1 = fmaf(c1, v1.y, a1);
                }
                if constexpr (S >= 2) {
                    float2 v2 = *(const float2*)(k2w + off);
                    a0 = fmaf(c2, v2.x, a0); a1 = fmaf(c2, v2.y, a1);
                }
                if constexpr (S >= 3) {
                    a0 = fmaf(c3, k3A[h][m], a0); a1 = fmaf(c3, k3A[h][m + 1], a1);
                }
                if constexpr (S >= 4) {
                    a0 = fmaf(c4, k4A[h][m], a0); a1 = fmaf(c4, k4A[h][m + 1], a1);
                }
                if constexpr (S >= 5) {
                    float2 v5 = *(const float2*)(k5w + off);
                    a0 = fmaf(c5, v5.x, a0); a1 = fmaf(c5, v5.y, a1);
                }
                __half2 hi = __floats2half2_rn(a0, a1);
                float2 hb = __half22float2(hi);
                __half2 lo = __floats2half2_rn(a0 - hb.x, a1 - hb.y);
                A1[kc][e * 2 + h] = *(uint32_t*)&hi;
                A2[kc][e * 2 + h] = *(uint32_t*)&lo;
            }

    float* dst = (S == 0) ? k1w : (S == 1) ? k2w : (S == 4) ? k5w : scw;

    // ---- MMA: 4 groups x {z j, g j, z j+1, g j+1}, 3 passes, K=16 ----
    #pragma unroll
    for (int grp = 0; grp < 4; grp++) {
        const int nb0 = 16 * grp + r0;      // z tile j
        const int nb2 = nb0 + 8;            // z tile j+1
        const int nb1 = 64 + nb0;           // g tile j
        const int nb3 = 64 + nb2;           // g tile j+1

        float d0[4] = {0,0,0,0}, d1[4] = {0,0,0,0};
        float d2[4] = {0,0,0,0}, d3[4] = {0,0,0,0};

        #pragma unroll
        for (int kc = 0; kc < 4; kc++) {
            const float4* Bp = BqT + (size_t)(kc * 4) * BQS;
            float4 q0 = Bp[nb0];
            float4 q1 = Bp[nb1];
            float4 q2 = Bp[nb2];
            float4 q3 = Bp[nb3];

            mma16(d0, A1[kc], __float_as_uint(q0.x), __float_as_uint(q0.y));  // HH
            mma16(d1, A1[kc], __float_as_uint(q1.x), __float_as_uint(q1.y));
            mma16(d2, A1[kc], __float_as_uint(q2.x), __float_as_uint(q2.y));
            mma16(d3, A1[kc], __float_as_uint(q3.x), __float_as_uint(q3.y));
            mma16(d0, A1[kc], __float_as_uint(q0.z), __float_as_uint(q0.w));  // HL
            mma16(d1, A1[kc], __float_as_uint(q1.z), __float_as_uint(q1.w));
            mma16(d2, A1[kc], __float_as_uint(q2.z), __float_as_uint(q2.w));
            mma16(d3, A1[kc], __float_as_uint(q3.z), __float_as_uint(q3.w));
            mma16(d0, A2[kc], __float_as_uint(q0.x), __float_as_uint(q0.y));  // LH
            mma16(d1, A2[kc], __float_as_uint(q1.x), __float_as_uint(q1.y));
            mma16(d2, A2[kc], __float_as_uint(q2.x), __float_as_uint(q2.y));
            mma16(d3, A2[kc], __float_as_uint(q3.x), __float_as_uint(q3.y));
        }

        const int nb = 16 * grp;
        {
            float bga = BG[nb + 2 * c0], bgb = BG[nb + 2 * c0 + 1];
            float kv0 = gelu_f(d0[0]) * timefac_f(d1[0] + bga);
            float kv1 = gelu_f(d0[1]) * timefac_f(d1[1] + bgb);
            float kv2 = gelu_f(d0[2]) * timefac_f(d1[2] + bga);
            float kv3 = gelu_f(d0[3]) * timefac_f(d1[3] + bgb);
            *(float2*)&dst[r0 * KSTR + nb + 2 * c0]       = make_float2(kv0, kv1);
            *(float2*)&dst[(r0 + 8) * KSTR + nb + 2 * c0] = make_float2(kv2, kv3);
        }
        {
            float bga = BG[nb + 8 + 2 * c0], bgb = BG[nb + 8 + 2 * c0 + 1];
            float kv0 = gelu_f(d2[0]) * timefac_f(d3[0] + bga);
            float kv1 = gelu_f(d2[1]) * timefac_f(d3[1] + bgb);
            float kv2 = gelu_f(d2[2]) * timefac_f(d3[2] + bga);
            float kv3 = gelu_f(d2[3]) * timefac_f(d3[3] + bgb);
            *(float2*)&dst[r0 * KSTR + nb + 8 + 2 * c0]       = make_float2(kv0, kv1);
            *(float2*)&dst[(r0 + 8) * KSTR + nb + 8 + 2 * c0] = make_float2(kv2, kv3);
        }
    }

    __syncwarp();

    // ---- stage epilogue ----
    if constexpr (S == 2) {
        #pragma unroll
        for (int h = 0; h < 2; h++)
            #pragma unroll
            for (int kc = 0; kc < 4; kc++)
                #pragma unroll
                for (int e = 0; e < 2; e++) {
                    const int m = kc * 4 + e * 2;
                    float2 v = *(const float2*)(scw + (r0 + 8 * h) * KSTR + 16 * kc + 8 * e + 2 * c0);
                    k3A[h][m] = v.x; k3A[h][m + 1] = v.y;
                }
    } else if constexpr (S == 3) {
        #pragma unroll
        for (int h = 0; h < 2; h++)
            #pragma unroll
            for (int kc = 0; kc < 4; kc++)
                #pragma unroll
                for (int e = 0; e < 2; e++) {
                    const int m = kc * 4 + e * 2;
                    float2 v = *(const float2*)(scw + (r0 + 8 * h) * KSTR + 16 * kc + 8 * e + 2 * c0);
                    k4A[h][m] = v.x; k4A[h][m + 1] = v.y;
                }
    } else if constexpr (S == 5) {
        constexpr float B0c = HC(35.0/384.0), B2c = HC(500.0/1113.0), B3c = HC(125.0/192.0),
                        B4c = HC(-2187.0/6784.0), B5c = HC(11.0/84.0);
        #pragma unroll
        for (int h = 0; h < 2; h++)
            #pragma unroll
            for (int kc = 0; kc < 4; kc++)
                #pragma unroll
                for (int e = 0; e < 2; e++) {
                    const int m = kc * 4 + e * 2;
                    const int off = (r0 + 8 * h) * KSTR + 16 * kc + 8 * e + 2 * c0;
                    float2 v1 = *(const float2*)(k1w + off);
                    float2 v5 = *(const float2*)(k5w + off);
                    float2 v6 = *(const float2*)(scw + off);
                    float a0 = xA[h][m], a1 = xA[h][m + 1];
                    a0 = fmaf(B0c, v1.x, a0);           a1 = fmaf(B0c, v1.y, a1);
                    a0 = fmaf(B2c, k3A[h][m], a0);      a1 = fmaf(B2c, k3A[h][m + 1], a1);
                    a0 = fmaf(B3c, k4A[h][m], a0);      a1 = fmaf(B3c, k4A[h][m + 1], a1);
                    a0 = fmaf(B4c, v5.x, a0);           a1 = fmaf(B4c, v5.y, a1);
                    xA[h][m]     = fmaf(B5c, v6.x, a0);
                    xA[h][m + 1] = fmaf(B5c, v6.y, a1);
                }
    }
    (void)last;
    __syncwarp();
}

__global__ __launch_bounds__(THREADS, 1)
void lif_hmma_kernel(const float* __restrict__ xin,
                     const float* __restrict__ W,
                     const float* __restrict__ Wg,
                     const float* __restrict__ bgp,
                     float* __restrict__ out,
                     int batch)
{
    float4* Bq = (float4*)(smf + OFF_BQ);
    float*  BG = smf + OFF_BG;

    const int tid = threadIdx.x;
    const int warp = tid >> 5, lane = tid & 31;
    const int r0 = lane >> 2;
    const int c0 = lane & 3;

    // ---- init B: fp16 hi/lo split of [W|Wg], fragment-packed for m16n8k16 ----
    for (int i = tid; i < 4096; i += THREADS) {
        int k = i >> 6, n = i & 63;
        int p = ((k >> 4) << 2) | ((k >> 1) & 3);
        int slot = ((k >> 3) & 1) * 2 + (k & 1);
        float w = W[i], g = Wg[i];
        __half wh = __float2half_rn(w);
        __half wl = __float2half_rn(w - __half2float(wh));
        __half gh = __float2half_rn(g);
        __half gl = __float2half_rn(g - __half2float(gh));
        __half* cw = (__half*)(Bq + p * BQS + n);
        __half* cg = (__half*)(Bq + p * BQS + 64 + n);
        cw[slot] = wh; cw[slot + 4] = wl;
        cg[slot] = gh; cg[slot + 4] = gl;
    }
    if (tid < 64) BG[tid] = bgp[tid];
    for (int i = tid; i < 4 * KBUF; i += THREADS) smf[OFF_K1 + i] = 0.0f;
    __syncthreads();

    float* k1w = smf + OFF_K1 + warp * 16 * KSTR;
    float* k2w = smf + OFF_K2 + warp * 16 * KSTR;
    float* scw = smf + OFF_SC + warp * 16 * KSTR;
    float* k5w = smf + OFF_K5 + warp * 16 * KSTR;

    const int rowbase = blockIdx.x * ROWS_CTA + warp * 16;

    float xA[2][16], k3A[2][16], k4A[2][16];
    #pragma unroll
    for (int h = 0; h < 2; h++) {
        int rr = rowbase + r0 + 8 * h;
        if (rr >= batch) rr = batch - 1;
        #pragma unroll
        for (int kc = 0; kc < 4; kc++)
            #pragma unroll
            for (int e = 0; e < 2; e++) {
                int m = kc * 4 + e * 2;
                int col = 16 * kc + 8 * e + 2 * c0;
                float2 v = *(const float2*)(xin + (size_t)rr * 64 + col);
                xA[h][m] = v.x; xA[h][m + 1] = v.y;
                k3A[h][m] = 0.f; k3A[h][m + 1] = 0.f;
                k4A[h][m] = 0.f; k4A[h][m + 1] = 0.f;
            }
    }

    const float4* BqT = Bq + c0 * BQS;

    #pragma unroll 1
    for (int step = 0; step < 8; step++) {
        stage_body<0>(xA, k3A, k4A, k1w, k2w, scw, k5w, BqT, BG, r0, c0, false);
        stage_body<1>(xA, k3A, k4A, k1w, k2w, scw, k5w, BqT, BG, r0, c0, false);
        stage_body<2>(xA, k3A, k4A, k1w, k2w, scw, k5w, BqT, BG, r0, c0, false);
        stage_body<3>(xA, k3A, k4A, k1w, k2w, scw, k5w, BqT, BG, r0, c0, false);
        stage_body<4>(xA, k3A, k4A, k1w, k2w, scw, k5w, BqT, BG, r0, c0, false);
        stage_body<5>(xA, k3A, k4A, k1w, k2w, scw, k5w, BqT, BG, r0, c0, step == 7);
    }

    // ---- spike output ----
    #pragma unroll
    for (int h = 0; h < 2; h++) {
        int rr = rowbase + r0 + 8 * h;
        if (rr < batch) {
            #pragma unroll
            for (int kc = 0; kc < 4; kc++)
                #pragma unroll
                for (int e = 0; e < 2; e++) {
                    const int m = kc * 4 + e * 2;
                    const int col = 16 * kc + 8 * e + 2 * c0;
                    float2 o;
                    o.x = ((xA[h][m]     - 0.3f) > 0.0f) ? 1.0f : 0.0f;
                    o.y = ((xA[h][m + 1] - 0.3f) > 0.0f) ? 1.0f : 0.0f;
                    *(float2*)(out + (size_t)rr * 64 + col) = o;
                }
        }
    }
}

extern "C" void kernel_launch(void* const* d_in, const int* in_sizes, int n_in,
                              void* d_out, int out_size)
{
    const float* x  = (const float*)d_in[0];   // [batch, 64]
    const float* W  = (const float*)d_in[1];   // [64, 64]
    const float* Wg = (const float*)d_in[2];   // [64, 64]
    const float* bg = (const float*)d_in[3];   // [64]
    float* out = (float*)d_out;

    const int smem_bytes = SMEM_FLOATS * 4;
    cudaFuncSetAttribute(lif_hmma_kernel, cudaFuncAttributeMaxDynamicSharedMemorySize, smem_bytes);

    int batch = in_sizes[0] / 64;
    int grid = (batch + ROWS_CTA - 1) / ROWS_CTA;
    lif_hmma_kernel<<<grid, THREADS, smem_bytes>>>(x, W, Wg, bg, out, batch);
}

// round 15
// speedup vs baseline: 1.1306x; 1.1306x over previous
#include <cuda_runtime.h>
#include <cuda_fp16.h>
#include <cstdint>

// LIFNeuron dopri5 via mma.sync m16n8k16 fp16 (2-term split, 3 passes) — R15.
// = R10 (13.73 ms) with ONLY NWARP 8 -> 10 (bisecting the R12 regression).

#define NWARP 10
#define THREADS (NWARP * 32)
#define ROWS_CTA (NWARP * 16)
#define BQS 130             // B row stride in float4
#define KSTR 72             // k-buffer row stride in floats (≡8 mod 32)

#define HC(x) (0.125f * (float)(x))

extern __shared__ float smf[];

#define OFF_BQ 0                          // 16 rows x BQS float4 = 8320 floats
#define OFF_K1 (16 * BQS * 4)
#define KBUF   (NWARP * 16 * KSTR)        // floats per buffer
#define OFF_K2 (OFF_K1 + KBUF)
#define OFF_SC (OFF_K2 + KBUF)
#define OFF_K5 (OFF_SC + KBUF)
#define OFF_BG (OFF_K5 + KBUF)
#define SMEM_FLOATS (OFF_BG + 64)         // 217856 B

__device__ __forceinline__ void mma16(float* d, const uint32_t* a, uint32_t b0, uint32_t b1) {
    asm volatile("mma.sync.aligned.m16n8k16.row.col.f32.f16.f16.f32 "
        "{%0,%1,%2,%3}, {%4,%5,%6,%7}, {%8,%9}, {%0,%1,%2,%3};"
        : "+f"(d[0]), "+f"(d[1]), "+f"(d[2]), "+f"(d[3])
        : "r"(a[0]), "r"(a[1]), "r"(a[2]), "r"(a[3]), "r"(b0), "r"(b1));
}

__device__ __forceinline__ float gelu_f(float z) {
    return 0.5f * z * (1.0f + erff(z * 0.70710678118654752440f));
}
__device__ __forceinline__ float timefac_f(float g) {
    float e = __expf(-g);
    return 1.0f - __frcp_rn(2.0f + e);
}

__global__ __launch_bounds__(THREADS, 1)
void lif_hmma_kernel(const float* __restrict__ xin,
                     const float* __restrict__ W,
                     const float* __restrict__ Wg,
                     const float* __restrict__ bgp,
                     float* __restrict__ out,
                     int batch)
{
    float4* Bq = (float4*)(smf + OFF_BQ);   // [p = kc*4+c0][n]: 8 halves {h1 k0,k0+1,k0+8,k0+9, h2 ...}
    float*  BG = smf + OFF_BG;

    const int tid = threadIdx.x;
    const int warp = tid >> 5, lane = tid & 31;
    const int r0 = lane >> 2;
    const int c0 = lane & 3;

    // ---- init B: fp16 hi/lo split of [W|Wg], fragment-packed for m16n8k16 ----
    for (int i = tid; i < 4096; i += THREADS) {
        int k = i >> 6, n = i & 63;
        int p = ((k >> 4) << 2) | ((k >> 1) & 3);
        int slot = ((k >> 3) & 1) * 2 + (k & 1);
        float w = W[i], g = Wg[i];
        __half wh = __float2half_rn(w);
        __half wl = __float2half_rn(w - __half2float(wh));
        __half gh = __float2half_rn(g);
        __half gl = __float2half_rn(g - __half2float(gh));
        __half* cw = (__half*)(Bq + p * BQS + n);
        __half* cg = (__half*)(Bq + p * BQS + 64 + n);
        cw[slot] = wh; cw[slot + 4] = wl;
        cg[slot] = gh; cg[slot + 4] = gl;
    }
    if (tid < 64) BG[tid] = bgp[tid];
    for (int i = tid; i < 4 * KBUF; i += THREADS) smf[OFF_K1 + i] = 0.0f;
    __syncthreads();

    float* k1w = smf + OFF_K1 + warp * 16 * KSTR;
    float* k2w = smf + OFF_K2 + warp * 16 * KSTR;
    float* scw = smf + OFF_SC + warp * 16 * KSTR;
    float* k5w = smf + OFF_K5 + warp * 16 * KSTR;

    const int rowbase = blockIdx.x * ROWS_CTA + warp * 16;

    // A-side state: xA[h][m], m = kc*4 + e*2 + d  ->  col = 16*kc + 8*e + 2*c0 + d
    float xA[2][16], k3A[2][16], k4A[2][16];
    #pragma unroll
    for (int h = 0; h < 2; h++) {
        int rr = rowbase + r0 + 8 * h;
        if (rr >= batch) rr = batch - 1;
        #pragma unroll
        for (int kc = 0; kc < 4; kc++)
            #pragma unroll
            for (int e = 0; e < 2; e++) {
                int m = kc * 4 + e * 2;
                int col = 16 * kc + 8 * e + 2 * c0;
                float2 v = *(const float2*)(xin + (size_t)rr * 64 + col);
                xA[h][m] = v.x; xA[h][m + 1] = v.y;
                k3A[h][m] = 0.f; k3A[h][m + 1] = 0.f;
                k4A[h][m] = 0.f; k4A[h][m + 1] = 0.f;
            }
    }

    const float B0c = HC(35.0/384.0), B2c = HC(500.0/1113.0), B3c = HC(125.0/192.0),
                B4c = HC(-2187.0/6784.0), B5c = HC(11.0/84.0);

    const float4* BqT = Bq + c0 * BQS;

    #pragma unroll 1
    for (int step = 0; step < 8; step++) {
        #pragma unroll 1
        for (int s = 0; s < 6; s++) {
            float c1, c2, c3, c4, c5;
            switch (s) {
                case 0:  c1 = 0.f;                 c2 = 0.f;                 c3 = 0.f;                c4 = 0.f;              c5 = 0.f; break;
                case 1:  c1 = HC(1.0/5.0);         c2 = 0.f;                 c3 = 0.f;                c4 = 0.f;              c5 = 0.f; break;
                case 2:  c1 = HC(3.0/40.0);        c2 = HC(9.0/40.0);        c3 = 0.f;                c4 = 0.f;              c5 = 0.f; break;
                case 3:  c1 = HC(44.0/45.0);       c2 = HC(-56.0/15.0);      c3 = HC(32.0/9.0);       c4 = 0.f;              c5 = 0.f; break;
                case 4:  c1 = HC(19372.0/6561.0);  c2 = HC(-25360.0/2187.0); c3 = HC(64448.0/6561.0); c4 = HC(-212.0/729.0); c5 = 0.f; break;
                default: c1 = HC(9017.0/3168.0);   c2 = HC(-355.0/33.0);     c3 = HC(46732.0/5247.0); c4 = HC(49.0/176.0);   c5 = HC(-5103.0/18656.0); break;
            }

            // ---- build xi, fp16 hi/lo split, packed A fragments ----
            uint32_t A1[4][4], A2[4][4];
            #pragma unroll
            for (int kc = 0; kc < 4; kc++)
                #pragma unroll
                for (int e = 0; e < 2; e++)
                    #pragma unroll
                    for (int h = 0; h < 2; h++) {
                        const int m = kc * 4 + e * 2;
                        const int off = (r0 + 8 * h) * KSTR + 16 * kc + 8 * e + 2 * c0;
                        float2 v1 = *(const float2*)(k1w + off);
                        float2 v2 = *(const float2*)(k2w + off);
                        float2 v5 = *(const float2*)(k5w + off);
                        float a0 = xA[h][m], a1 = xA[h][m + 1];
                        a0 = fmaf(c1, v1.x, a0);            a1 = fmaf(c1, v1.y, a1);
                        a0 = fmaf(c2, v2.x, a0);            a1 = fmaf(c2, v2.y, a1);
                        a0 = fmaf(c3, k3A[h][m], a0);       a1 = fmaf(c3, k3A[h][m + 1], a1);
                        a0 = fmaf(c4, k4A[h][m], a0);       a1 = fmaf(c4, k4A[h][m + 1], a1);
                        a0 = fmaf(c5, v5.x, a0);            a1 = fmaf(c5, v5.y, a1);
                        __half2 hi = __floats2half2_rn(a0, a1);
                        float2 hb = __half22float2(hi);
                        __half2 lo = __floats2half2_rn(a0 - hb.x, a1 - hb.y);
                        A1[kc][e * 2 + h] = *(uint32_t*)&hi;
                        A2[kc][e * 2 + h] = *(uint32_t*)&lo;
                    }

            float* dst = (s == 0) ? k1w : (s == 1) ? k2w : (s == 4) ? k5w : scw;

            // ---- MMA: 4 groups x {z j, g j, z j+1, g j+1}, 3 passes, K=16 ----
            #pragma unroll
            for (int grp = 0; grp < 4; grp++) {
                const int nb0 = 16 * grp + r0;      // z tile j
                const int nb2 = nb0 + 8;            // z tile j+1
                const int nb1 = 64 + nb0;           // g tile j
                const int nb3 = 64 + nb2;           // g tile j+1

                float d0[4] = {0,0,0,0}, d1[4] = {0,0,0,0};
                float d2[4] = {0,0,0,0}, d3[4] = {0,0,0,0};

                #pragma unroll
                for (int kc = 0; kc < 4; kc++) {
                    const float4* Bp = BqT + (size_t)(kc * 4) * BQS;
                    float4 q0 = Bp[nb0];   // {B1 pair k0, B1 pair k0+8, B2 pair k0, B2 pair k0+8}
                    float4 q1 = Bp[nb1];
                    float4 q2 = Bp[nb2];
                    float4 q3 = Bp[nb3];

                    mma16(d0, A1[kc], __float_as_uint(q0.x), __float_as_uint(q0.y));  // HH
                    mma16(d1, A1[kc], __float_as_uint(q1.x), __float_as_uint(q1.y));
                    mma16(d2, A1[kc], __float_as_uint(q2.x), __float_as_uint(q2.y));
                    mma16(d3, A1[kc], __float_as_uint(q3.x), __float_as_uint(q3.y));
                    mma16(d0, A1[kc], __float_as_uint(q0.z), __float_as_uint(q0.w));  // HL
                    mma16(d1, A1[kc], __float_as_uint(q1.z), __float_as_uint(q1.w));
                    mma16(d2, A1[kc], __float_as_uint(q2.z), __float_as_uint(q2.w));
                    mma16(d3, A1[kc], __float_as_uint(q3.z), __float_as_uint(q3.w));
                    mma16(d0, A2[kc], __float_as_uint(q0.x), __float_as_uint(q0.y));  // LH
                    mma16(d1, A2[kc], __float_as_uint(q1.x), __float_as_uint(q1.y));
                    mma16(d2, A2[kc], __float_as_uint(q2.x), __float_as_uint(q2.y));
                    mma16(d3, A2[kc], __float_as_uint(q3.x), __float_as_uint(q3.y));
                }

                const int nb = 16 * grp;
                {
                    float bga = BG[nb + 2 * c0], bgb = BG[nb + 2 * c0 + 1];
                    float kv0 = gelu_f(d0[0]) * timefac_f(d1[0] + bga);
                    float kv1 = gelu_f(d0[1]) * timefac_f(d1[1] + bgb);
                    float kv2 = gelu_f(d0[2]) * timefac_f(d1[2] + bga);
                    float kv3 = gelu_f(d0[3]) * timefac_f(d1[3] + bgb);
                    *(float2*)&dst[r0 * KSTR + nb + 2 * c0]       = make_float2(kv0, kv1);
                    *(float2*)&dst[(r0 + 8) * KSTR + nb + 2 * c0] = make_float2(kv2, kv3);
                }
                {
                    float bga = BG[nb + 8 + 2 * c0], bgb = BG[nb + 8 + 2 * c0 + 1];
                    float kv0 = gelu_f(d2[0]) * timefac_f(d3[0] + bga);
                    float kv1 = gelu_f(d2[1]) * timefac_f(d3[1] + bgb);
                    float kv2 = gelu_f(d2[2]) * timefac_f(d3[2] + bga);
                    float kv3 = gelu_f(d2[3]) * timefac_f(d3[3] + bgb);
                    *(float2*)&dst[r0 * KSTR + nb + 8 + 2 * c0]       = make_float2(kv0, kv1);
                    *(float2*)&dst[(r0 + 8) * KSTR + nb + 8 + 2 * c0] = make_float2(kv2, kv3);
                }
            }

            __syncwarp();

            // ---- stage epilogue (paired loads) ----
            if (s == 2) {
                #pragma unroll
                for (int h = 0; h < 2; h++)
                    #pragma unroll
                    for (int kc = 0; kc < 4; kc++)
                        #pragma unroll
                        for (int e = 0; e < 2; e++) {
                            const int m = kc * 4 + e * 2;
                            float2 v = *(const float2*)(scw + (r0 + 8 * h) * KSTR + 16 * kc + 8 * e + 2 * c0);
                            k3A[h][m] = v.x; k3A[h][m + 1] = v.y;
                        }
            } else if (s == 3) {
                #pragma unroll
                for (int h = 0; h < 2; h++)
                    #pragma unroll
                    for (int kc = 0; kc < 4; kc++)
                        #pragma unroll
                        for (int e = 0; e < 2; e++) {
                            const int m = kc * 4 + e * 2;
                            float2 v = *(const float2*)(scw + (r0 + 8 * h) * KSTR + 16 * kc + 8 * e + 2 * c0);
                            k4A[h][m] = v.x; k4A[h][m + 1] = v.y;
                        }
            } else if (s == 5) {
                #pragma unroll
                for (int h = 0; h < 2; h++)
                    #pragma unroll
                    for (int kc = 0; kc < 4; kc++)
                        #pragma unroll
                        for (int e = 0; e < 2; e++) {
                            const int m = kc * 4 + e * 2;
                            const int off = (r0 + 8 * h) * KSTR + 16 * kc + 8 * e + 2 * c0;
                            float2 v1 = *(const float2*)(k1w + off);
                            float2 v5 = *(const float2*)(k5w + off);
                            float2 v6 = *(const float2*)(scw + off);
                            float a0 = xA[h][m], a1 = xA[h][m + 1];
                            a0 = fmaf(B0c, v1.x, a0);           a1 = fmaf(B0c, v1.y, a1);
                            a0 = fmaf(B2c, k3A[h][m], a0);      a1 = fmaf(B2c, k3A[h][m + 1], a1);
                            a0 = fmaf(B3c, k4A[h][m], a0);      a1 = fmaf(B3c, k4A[h][m + 1], a1);
                            a0 = fmaf(B4c, v5.x, a0);           a1 = fmaf(B4c, v5.y, a1);
                            xA[h][m]     = fmaf(B5c, v6.x, a0);
                            xA[h][m + 1] = fmaf(B5c, v6.y, a1);
                        }
            }
            __syncwarp();
        }
    }

    // ---- spike output ----
    #pragma unroll
    for (int h = 0; h < 2; h++) {
        int rr = rowbase + r0 + 8 * h;
        if (rr < batch) {
            #pragma unroll
            for (int kc = 0; kc < 4; kc++)
                #pragma unroll
                for (int e = 0; e < 2; e++) {
                    const int m = kc * 4 + e * 2;
                    const int col = 16 * kc + 8 * e + 2 * c0;
                    float2 o;
                    o.x = ((xA[h][m]     - 0.3f) > 0.0f) ? 1.0f : 0.0f;
                    o.y = ((xA[h][m + 1] - 0.3f) > 0.0f) ? 1.0f : 0.0f;
                    *(float2*)(out + (size_t)rr * 64 + col) = o;
                }
        }
    }
}

extern "C" void kernel_launch(void* const* d_in, const int* in_sizes, int n_in,
                              void* d_out, int out_size)
{
    const float* x  = (const float*)d_in[0];   // [batch, 64]
    const float* W  = (const float*)d_in[1];   // [64, 64]
    const float* Wg = (const float*)d_in[2];   // [64, 64]
    const float* bg = (const float*)d_in[3];   // [64]
    float* out = (float*)d_out;

    const int smem_bytes = SMEM_FLOATS * 4;
    cudaFuncSetAttribute(lif_hmma_kernel, cudaFuncAttributeMaxDynamicSharedMemorySize, smem_bytes);

    int batch = in_sizes[0] / 64;
    int grid = (batch + ROWS_CTA - 1) / ROWS_CTA;
    lif_hmma_kernel<<<grid, THREADS, smem_bytes>>>(x, W, Wg, bg, out, batch);
}